// round 17
// baseline (speedup 1.0000x reference)
#include <cuda_runtime.h>
#include <cuda_fp16.h>
#include <stdint.h>

// Grouped GEMM out[e] = x[e] @ w[e]^T, fp32 I/O; E=16, M=256, K=2048, N=8192.
// R14, two kernels:
//  1) cvt pre-pass: X, W fp32 -> fp16 into __device__ scratch (streaming).
//  2) GEMM: single-pass fp16 mma.sync, fp32 accumulate, cp.async.cg 16B
//     gmem->smem 3-stage pipeline (no in-loop converts / STS / register
//     staging — the L1 round-trip was the measured wall at 86-94%).
// rel_err model (calibrated R12/R13): fp16 rounding of A and B ~ 2.9e-4.
// Main kernel: 512 thr / 16 warps (2x8), warp tile 64x32, CTA tile 128x256,
// KC=64, 144B padded rows (16B-aligned, conflict-free ldmatrix + fills).

static constexpr int E_DIM = 16;
static constexpr int M_DIM = 256;
static constexpr int K_DIM = 2048;
static constexpr int N_DIM = 8192;

static constexpr int BM = 128;
static constexpr int BN = 256;
static constexpr int KC = 64;                 // k per chunk (fp16: 128 B/row)
static constexpr int NCHUNK = K_DIM / KC;     // 32
static constexpr int NSTAGE = 3;

static constexpr int ROW_B   = 144;           // 128 B payload + 16 B pad
static constexpr int A_TILE  = 128 * ROW_B;   // 18432 B
static constexpr int B_TILE  = 256 * ROW_B;   // 36864 B
static constexpr int OFF_A   = 0;
static constexpr int OFF_B   = A_TILE;
static constexpr int STAGE_B = A_TILE + B_TILE;   // 55296
static constexpr int SMEM_B  = NSTAGE * STAGE_B;  // 165888

// fp16 scratch (module-scope device arrays; allowed scratch mechanism)
static constexpr size_t XH_N = (size_t)E_DIM * M_DIM * K_DIM;   //   8.4 M
static constexpr size_t WH_N = (size_t)E_DIM * N_DIM * K_DIM;   // 268.4 M
__device__ __align__(16) __half Xh_buf[XH_N];
__device__ __align__(16) __half Wh_buf[WH_N];

// ---------------- pre-pass: fp32 -> fp16 ----------------

__global__ void cvt_x_kernel(const float* __restrict__ src) {
    size_t i = (size_t)blockIdx.x * blockDim.x + threadIdx.x;
    const size_t n4 = XH_N / 4;
    const size_t stride = (size_t)gridDim.x * blockDim.x;
    for (; i < n4; i += stride) {
        float4 v = reinterpret_cast<const float4*>(src)[i];
        __half2 a = __floats2half2_rn(v.x, v.y);
        __half2 b = __floats2half2_rn(v.z, v.w);
        reinterpret_cast<uint2*>(Xh_buf)[i] =
            make_uint2(*reinterpret_cast<uint32_t*>(&a),
                       *reinterpret_cast<uint32_t*>(&b));
    }
}

__global__ void cvt_w_kernel(const float* __restrict__ src) {
    size_t i = (size_t)blockIdx.x * blockDim.x + threadIdx.x;
    const size_t n4 = WH_N / 4;
    const size_t stride = (size_t)gridDim.x * blockDim.x;
    for (; i < n4; i += stride) {
        float4 v = reinterpret_cast<const float4*>(src)[i];
        __half2 a = __floats2half2_rn(v.x, v.y);
        __half2 b = __floats2half2_rn(v.z, v.w);
        reinterpret_cast<uint2*>(Wh_buf)[i] =
            make_uint2(*reinterpret_cast<uint32_t*>(&a),
                       *reinterpret_cast<uint32_t*>(&b));
    }
}

// ---------------- main GEMM ----------------

__device__ __forceinline__ uint32_t smem_u32(const void* p) {
    uint32_t a;
    asm("{ .reg .u64 t; cvta.to.shared.u64 t, %1; cvt.u32.u64 %0, t; }"
        : "=r"(a) : "l"(p));
    return a;
}

__device__ __forceinline__ void cp16(uint32_t dst, const void* src) {
    asm volatile("cp.async.cg.shared.global [%0], [%1], 16;"
                 :: "r"(dst), "l"(src) : "memory");
}
__device__ __forceinline__ void cp_commit() {
    asm volatile("cp.async.commit_group;" ::: "memory");
}
template <int N>
__device__ __forceinline__ void cp_wait() {
    asm volatile("cp.async.wait_group %0;" :: "n"(N) : "memory");
}

__device__ __forceinline__ void ldsm4(uint32_t* r, uint32_t addr) {
    asm volatile("ldmatrix.sync.aligned.m8n8.x4.shared.b16 {%0,%1,%2,%3}, [%4];"
                 : "=r"(r[0]), "=r"(r[1]), "=r"(r[2]), "=r"(r[3]) : "r"(addr));
}

__device__ __forceinline__ void mma16816(float* c, const uint32_t* a,
                                         const uint32_t* b) {
    asm volatile(
        "mma.sync.aligned.m16n8k16.row.col.f32.f16.f16.f32 "
        "{%0,%1,%2,%3}, {%4,%5,%6,%7}, {%8,%9}, {%0,%1,%2,%3};"
        : "+f"(c[0]), "+f"(c[1]), "+f"(c[2]), "+f"(c[3])
        : "r"(a[0]), "r"(a[1]), "r"(a[2]), "r"(a[3]), "r"(b[0]), "r"(b[1]));
}

__global__ __launch_bounds__(512, 1)
void grouped_gemm_hmma(float* __restrict__ O) {
    extern __shared__ char sm[];
    const uint32_t sbase = smem_u32(sm);

    const int tid  = threadIdx.x;
    const int wid  = tid >> 5;
    const int lane = tid & 31;
    const int wm   = wid >> 3;   // 0..1 -> 64-row slab
    const int wn   = wid & 7;    // 0..7 -> 32-col slab

    const int e  = blockIdx.z;
    const int m0 = blockIdx.y * BM;
    const int n0 = blockIdx.x * BN;

    // ---- cp.async load mapping (fp16 gmem, k-contiguous rows) ----
    // A: 128 rows x 128 B; 4 threads/row, each 32 B (2 x 16B segs)
    const int arow = tid >> 2;
    const int aseg = tid & 3;                // 32B segment pair index
    const __half* Agh = Xh_buf + ((size_t)e * M_DIM + m0 + arow) * K_DIM + aseg * 16;
    const uint32_t wbA = (uint32_t)(arow * ROW_B + aseg * 32);
    // B: 256 rows x 128 B; 2 threads/row, each 64 B (4 x 16B segs)
    const int brow = tid >> 1;
    const int bhf  = tid & 1;
    const __half* Bgh = Wh_buf + ((size_t)e * N_DIM + n0 + brow) * K_DIM + bhf * 32;
    const uint32_t wbB = (uint32_t)(brow * ROW_B + bhf * 64);

    // ---- ldmatrix offsets within a stage (ks-step = +32 B) ----
    const uint32_t aoff = (uint32_t)((wm * 64 + (lane & 15)) * ROW_B + ((lane >> 4) << 4));
    const uint32_t boff = (uint32_t)((wn * 32 + ((lane >> 4) << 3) + (lane & 7)) * ROW_B
                                     + (((lane >> 3) & 1) << 4));

    float acc[4][4][4];
#pragma unroll
    for (int i = 0; i < 4; i++)
#pragma unroll
        for (int j = 0; j < 4; j++)
#pragma unroll
            for (int v = 0; v < 4; v++) acc[i][j][v] = 0.0f;

    // issue one chunk's loads into stage buffer s
    auto load_chunk = [&](int c, int s) {
        const uint32_t st = sbase + (uint32_t)(s * STAGE_B);
        const size_t kof = (size_t)c * KC;
        cp16(st + OFF_A + wbA,      Agh + kof);
        cp16(st + OFF_A + wbA + 16, Agh + kof + 8);
#pragma unroll
        for (int j = 0; j < 4; j++)
            cp16(st + OFF_B + wbB + j * 16, Bgh + kof + j * 8);
    };

    // ---- prologue: stages 0,1 in flight ----
    load_chunk(0, 0); cp_commit();
    load_chunk(1, 1); cp_commit();

#pragma unroll 1
    for (int c = 0; c < NCHUNK; c++) {
        cp_wait<1>();          // oldest pending group (chunk c) complete
        __syncthreads();

        const uint32_t st = sbase + (uint32_t)((c % NSTAGE) * STAGE_B);
        const uint32_t As = st + OFF_A, Bs = st + OFF_B;

#pragma unroll
        for (int ks = 0; ks < 4; ks++) {
            const uint32_t ksb = ks * 32;
            uint32_t bf[8];
#pragma unroll
            for (int np = 0; np < 2; np++)
                ldsm4(bf + 4 * np, Bs + boff + np * (16 * ROW_B) + ksb);
#pragma unroll
            for (int mt = 0; mt < 4; mt++) {
                uint32_t ah[4];
                ldsm4(ah, As + aoff + mt * (16 * ROW_B) + ksb);
#pragma unroll
                for (int nt = 0; nt < 4; nt++)
                    mma16816(acc[mt][nt], ah, bf + 2 * nt);
            }
        }

        // refill the stage consumed two iterations ago (safe: all warps
        // passed this iteration's __syncthreads after finishing it)
        if (c + 2 < NCHUNK) load_chunk(c + 2, (c + 2) % NSTAGE);
        cp_commit();           // unconditional: keeps group accounting uniform
    }

    // ---- epilogue ----
    float* C = O + (size_t)e * M_DIM * N_DIM;
    const int mrow = m0 + wm * 64 + (lane >> 2);
    const int ncol = n0 + wn * 32 + (lane & 3) * 2;
#pragma unroll
    for (int mt = 0; mt < 4; mt++) {
#pragma unroll
        for (int nt = 0; nt < 4; nt++) {
            float* p0 = C + (size_t)(mrow + mt * 16) * N_DIM + (ncol + nt * 8);
            float* p1 = p0 + 8 * N_DIM;
            *reinterpret_cast<float2*>(p0) = make_float2(acc[mt][nt][0], acc[mt][nt][1]);
            *reinterpret_cast<float2*>(p1) = make_float2(acc[mt][nt][2], acc[mt][nt][3]);
        }
    }
}

extern "C" void kernel_launch(void* const* d_in, const int* in_sizes, int n_in,
                              void* d_out, int out_size) {
    const float* X = (const float*)d_in[0];  // expert_inputs  [E, M, K]
    const float* W = (const float*)d_in[1];  // expert_weights [E, N, K]
    float* O = (float*)d_out;                // [E, M, N]

    // pre-pass: fp32 -> fp16 scratch
    cvt_x_kernel<<<2048, 256>>>(X);
    cvt_w_kernel<<<16384, 256>>>(W);

    cudaFuncSetAttribute(grouped_gemm_hmma,
                         cudaFuncAttributeMaxDynamicSharedMemorySize, SMEM_B);

    dim3 grid(N_DIM / BN, M_DIM / BM, E_DIM);  // (32, 2, 16) = 1024 CTAs
    grouped_gemm_hmma<<<grid, 512, SMEM_B>>>(O);
}